// round 1
// baseline (speedup 1.0000x reference)
#include <cuda_runtime.h>

#define W 15            // attention block length
#define DIM 64          // head dim
#define BLK_PER_CTA 4   // attention blocks per CTA
#define NTHREADS 64     // 2 warps; each warp serves 2 attention blocks
#define SSTRIDE 964     // floats per block in smem (960 + 4 pad -> bank shift)
#define EPS 1e-6f

typedef unsigned long long ull;

__device__ __forceinline__ ull pack2(float lo, float hi) {
    ull r; asm("mov.b64 %0, {%1,%2};" : "=l"(r) : "f"(lo), "f"(hi)); return r;
}
__device__ __forceinline__ void unpack2(ull v, float& lo, float& hi) {
    asm("mov.b64 {%0,%1}, %2;" : "=f"(lo), "=f"(hi) : "l"(v));
}
__device__ __forceinline__ ull fma2(ull a, ull b, ull c) {
    ull d; asm("fma.rn.f32x2 %0, %1, %2, %3;" : "=l"(d) : "l"(a), "l"(b), "l"(c)); return d;
}
__device__ __forceinline__ ull mul2(ull a, ull b) {
    ull d; asm("mul.rn.f32x2 %0, %1, %2;" : "=l"(d) : "l"(a), "l"(b)); return d;
}

__global__ void __launch_bounds__(NTHREADS)
robust_attn_kernel(const float* __restrict__ q, const float* __restrict__ k,
                   const float* __restrict__ v, float* __restrict__ out, int G)
{
    __shared__ float sK[BLK_PER_CTA * SSTRIDE];
    __shared__ float sV[BLK_PER_CTA * SSTRIDE];
    __shared__ float stab[16];   // cos((i-j)*pi/30); entry 15 = guard for speculation

    const int tid = threadIdx.x;
    const int gblk0 = blockIdx.x * BLK_PER_CTA;
    const int nvalid = min(BLK_PER_CTA, G - gblk0);
    const size_t base0 = (size_t)gblk0 * (W * DIM);

    if (tid < 16) stab[tid] = (tid < W) ? cosf((float)tid * 0.10471975511965977f) : 0.f;

    // ---- cooperative fill of K,V (relu applied once here) ----
    const int nflt = nvalid * (W * DIM);
    const float4* gk = (const float4*)(k + base0);
    const float4* gv = (const float4*)(v + base0);
    #pragma unroll
    for (int it = 0; it < (BLK_PER_CTA * W * DIM / 4) / NTHREADS; ++it) {
        int i4 = it * NTHREADS + tid;
        int flat = i4 * 4;
        if (flat < nflt) {
            int lb  = flat / (W * DIM);
            int pos = flat - lb * (W * DIM);
            float4 a = gk[i4];
            a.x = fmaxf(a.x, 0.f); a.y = fmaxf(a.y, 0.f);
            a.z = fmaxf(a.z, 0.f); a.w = fmaxf(a.w, 0.f);
            *(float4*)&sK[lb * SSTRIDE + pos] = a;
            float4 b = gv[i4];
            b.x = fmaxf(b.x, 0.f); b.y = fmaxf(b.y, 0.f);
            b.z = fmaxf(b.z, 0.f); b.w = fmaxf(b.w, 0.f);
            *(float4*)&sV[lb * SSTRIDE + pos] = b;
        }
    }
    __syncthreads();

    // ---- lane -> (local block, query row) ----
    const int lane = tid & 31;
    const int warp = tid >> 5;
    const int half = lane >> 4;
    const int lb   = warp * 2 + half;          // local attention block 0..3
    const int row  = lane & 15;                // 0..15; 15 is a spare lane
    const int i    = (row < W) ? row : (W - 1);
    const bool store_ok = (row < W) && (lb < nvalid);
    const int lbc = (lb < nvalid) ? lb : 0;    // clamp for safe addressing
    const size_t blkbase = base0 + (size_t)lbc * (W * DIM);

    // ---- load + relu my q row into packed f32x2 registers ----
    ull q2[DIM / 2];
    const float4* qr = (const float4*)(q + blkbase + i * DIM);
    #pragma unroll
    for (int c = 0; c < DIM / 4; ++c) {
        float4 t = qr[c];
        q2[2 * c]     = pack2(fmaxf(t.x, 0.f), fmaxf(t.y, 0.f));
        q2[2 * c + 1] = pack2(fmaxf(t.z, 0.f), fmaxf(t.w, 0.f));
    }

    // ---- phase A: scores s[j] = (q_i . k_j) * cos((i-j)*pi/30), causal ----
    float s[W];
    float denom = 0.f;
    #pragma unroll
    for (int j = 0; j < W; ++j) {
        const ulonglong2* kr = (const ulonglong2*)&sK[lbc * SSTRIDE + j * DIM];
        ull a0 = 0ULL, a1 = 0ULL;
        #pragma unroll
        for (int c = 0; c < DIM / 4; ++c) {
            ulonglong2 t = kr[c];
            a0 = fma2(q2[2 * c],     t.x, a0);
            a1 = fma2(q2[2 * c + 1], t.y, a1);
        }
        float x0, x1, y0, y1;
        unpack2(a0, x0, x1); unpack2(a1, y0, y1);
        float dot = (x0 + x1) + (y0 + y1);
        int dd = i - j;
        float sj = (dd >= 0) ? dot * stab[dd & 15] : 0.f;
        s[j] = sj;
        denom += sj;
    }
    const float rd = 1.0f / fmaxf(denom, EPS);
    const ull rd2 = pack2(rd, rd);

    ull s2[W];
    #pragma unroll
    for (int j = 0; j < W; ++j) s2[j] = pack2(s[j], s[j]);

    // ---- phase B: out_i = (sum_j s[j] * v_j) * rd, chunked over d ----
    float* op = out + blkbase + i * DIM;
    #pragma unroll
    for (int ch = 0; ch < 4; ++ch) {
        ull acc[8];
        #pragma unroll
        for (int e = 0; e < 8; ++e) acc[e] = 0ULL;
        #pragma unroll
        for (int j = 0; j < W; ++j) {
            const ulonglong2* vr = (const ulonglong2*)&sV[lbc * SSTRIDE + j * DIM + ch * 16];
            ulonglong2 t0 = vr[0], t1 = vr[1];
            acc[0] = fma2(s2[j], t0.x, acc[0]);
            acc[1] = fma2(s2[j], t0.y, acc[1]);
            acc[2] = fma2(s2[j], t1.x, acc[2]);
            acc[3] = fma2(s2[j], t1.y, acc[3]);
            ulonglong2 t2 = vr[2], t3 = vr[3];
            acc[4] = fma2(s2[j], t2.x, acc[4]);
            acc[5] = fma2(s2[j], t2.y, acc[5]);
            acc[6] = fma2(s2[j], t3.x, acc[6]);
            acc[7] = fma2(s2[j], t3.y, acc[7]);
        }
        if (store_ok) {
            ulonglong2* od = (ulonglong2*)(op + ch * 16);
            ulonglong2 o;
            o.x = mul2(acc[0], rd2); o.y = mul2(acc[1], rd2); od[0] = o;
            o.x = mul2(acc[2], rd2); o.y = mul2(acc[3], rd2); od[1] = o;
            o.x = mul2(acc[4], rd2); o.y = mul2(acc[5], rd2); od[2] = o;
            o.x = mul2(acc[6], rd2); o.y = mul2(acc[7], rd2); od[3] = o;
        }
    }
}

extern "C" void kernel_launch(void* const* d_in, const int* in_sizes, int n_in,
                              void* d_out, int out_size) {
    const float* q = (const float*)d_in[0];
    const float* k = (const float*)d_in[1];
    const float* v = (const float*)d_in[2];
    float* out = (float*)d_out;

    int n = in_sizes[0];            // B*H*L*D
    int G = n / (W * DIM);          // number of attention blocks (20480)
    int grid = (G + BLK_PER_CTA - 1) / BLK_PER_CTA;
    robust_attn_kernel<<<grid, NTHREADS>>>(q, k, v, out, G);
}

// round 2
// speedup vs baseline: 1.2509x; 1.2509x over previous
#include <cuda_runtime.h>

#define W 15            // attention block length
#define DIM 64          // head dim
#define WARPS_PER_CTA 4
#define NTHREADS 128
#define EPS 1e-6f

typedef unsigned long long ull;

__device__ __forceinline__ ull pack2(float lo, float hi) {
    ull r; asm("mov.b64 %0, {%1,%2};" : "=l"(r) : "f"(lo), "f"(hi)); return r;
}
__device__ __forceinline__ void unpack2(ull v, float& lo, float& hi) {
    asm("mov.b64 {%0,%1}, %2;" : "=f"(lo), "=f"(hi) : "l"(v));
}
__device__ __forceinline__ ull fma2(ull a, ull b, ull c) {
    ull d; asm("fma.rn.f32x2 %0, %1, %2, %3;" : "=l"(d) : "l"(a), "l"(b), "l"(c)); return d;
}
__device__ __forceinline__ ull mul2(ull a, ull b) {
    ull d; asm("mul.rn.f32x2 %0, %1, %2;" : "=l"(d) : "l"(a), "l"(b)); return d;
}
__device__ __forceinline__ float shxor(float v, int m) {
    return __shfl_xor_sync(0xffffffffu, v, m, 32);
}

// angle-step literals (phi = pi/30 per index step)
#define CA1 0.994521895368273f   // cos(pi/30)  = cos 6 deg
#define SA1 0.104528463267653f   // sin(pi/30)
#define CA4 0.913545457642601f   // cos(4*pi/30) = cos 24 deg
#define SA4 0.406736643075800f   // sin(24 deg)
#define CG2 0.978147600733806f   // cos 12
#define SG2 0.207911690817759f
#define CG3 0.951056516295154f   // cos 18
#define SG3 0.309016994374947f

__global__ void __launch_bounds__(NTHREADS, 4)
robust_attn_kernel(const float* __restrict__ q, const float* __restrict__ k,
                   const float* __restrict__ v, float* __restrict__ out, int G)
{
    const int wid = blockIdx.x * WARPS_PER_CTA + (threadIdx.x >> 5);
    if (wid >= G) return;

    const int lane = threadIdx.x & 31;
    const int g = lane & 3;       // row-group: rows g, g+4, g+8, g+12
    const int d = lane >> 2;      // dim-group: dims [8d, 8d+8)
    const size_t base = (size_t)wid * (W * DIM);
    const int doff = d * 8;

    // ---- per-lane cos/sin of own row angles: phi_i = i*pi/30, i = g+4t ----
    float cg = (g == 0) ? 1.0f : (g == 1) ? CA1 : (g == 2) ? CG2 : CG3;
    float sg = (g == 0) ? 0.0f : (g == 1) ? SA1 : (g == 2) ? SG2 : SG3;
    float ci[4], si[4];
    ci[0] = cg; si[0] = sg;
    #pragma unroll
    for (int t = 1; t < 4; ++t) {
        ci[t] = ci[t-1] * CA4 - si[t-1] * SA4;
        si[t] = si[t-1] * CA4 + ci[t-1] * SA4;
    }

    // ---- load + relu q slices for my 4 rows (row 15 clamped; masked at store) ----
    ull q2[4][4];
    #pragma unroll
    for (int t = 0; t < 4; ++t) {
        int row = g + 4 * t; if (row > W - 1) row = W - 1;
        const float4* qp = (const float4*)(q + base + row * DIM + doff);
        float4 a = qp[0], b = qp[1];
        q2[t][0] = pack2(fmaxf(a.x, 0.f), fmaxf(a.y, 0.f));
        q2[t][1] = pack2(fmaxf(a.z, 0.f), fmaxf(a.w, 0.f));
        q2[t][2] = pack2(fmaxf(b.x, 0.f), fmaxf(b.y, 0.f));
        q2[t][3] = pack2(fmaxf(b.z, 0.f), fmaxf(b.w, 0.f));
    }

    ull acc[4][4];
    #pragma unroll
    for (int t = 0; t < 4; ++t)
        #pragma unroll
        for (int e = 0; e < 4; ++e) acc[t][e] = 0ULL;
    float dn[4] = {0.f, 0.f, 0.f, 0.f};

    // ---- single fused pass over j: K,V each read exactly once per warp ----
    float cj = 1.0f, sj = 0.0f;   // cos/sin(j*pi/30)
    #pragma unroll
    for (int j = 0; j < W; ++j) {
        const float4* kp = (const float4*)(k + base + j * DIM + doff);
        float4 k0 = kp[0], k1 = kp[1];
        const float4* vp = (const float4*)(v + base + j * DIM + doff);
        float4 v0 = vp[0], v1 = vp[1];

        ull ka = pack2(fmaxf(k0.x, 0.f), fmaxf(k0.y, 0.f));
        ull kb = pack2(fmaxf(k0.z, 0.f), fmaxf(k0.w, 0.f));
        ull kc = pack2(fmaxf(k1.x, 0.f), fmaxf(k1.y, 0.f));
        ull kd = pack2(fmaxf(k1.z, 0.f), fmaxf(k1.w, 0.f));
        ull va = pack2(fmaxf(v0.x, 0.f), fmaxf(v0.y, 0.f));
        ull vb = pack2(fmaxf(v0.z, 0.f), fmaxf(v0.w, 0.f));
        ull vc = pack2(fmaxf(v1.x, 0.f), fmaxf(v1.y, 0.f));
        ull vd = pack2(fmaxf(v1.z, 0.f), fmaxf(v1.w, 0.f));

        #pragma unroll
        for (int t = 0; t < 4; ++t) {
            if (4 * t + 3 >= j) {          // compile-time skip of impossible pairs
                // partial dot over my 8 dims
                ull p = mul2(q2[t][0], ka);
                p = fma2(q2[t][1], kb, p);
                p = fma2(q2[t][2], kc, p);
                p = fma2(q2[t][3], kd, p);
                float pl, ph; unpack2(p, pl, ph);
                float pf = pl + ph;
                // reduce over 8 dim-groups (lanes differing in bits 2..4)
                pf += shxor(pf, 4);
                pf += shxor(pf, 8);
                pf += shxor(pf, 16);
                // cos reweight: cos(phi_i - phi_j) = ci*cj + si*sj
                float s = pf * (ci[t] * cj + si[t] * sj);
                // runtime causality only where it depends on g
                if (4 * t < j) s = (g >= j - 4 * t) ? s : 0.f;
                dn[t] += s;
                ull s2 = pack2(s, s);
                acc[t][0] = fma2(s2, va, acc[t][0]);
                acc[t][1] = fma2(s2, vb, acc[t][1]);
                acc[t][2] = fma2(s2, vc, acc[t][2]);
                acc[t][3] = fma2(s2, vd, acc[t][3]);
            }
        }
        // advance cos/sin(j*pi/30) -> ((j+1)*pi/30)
        float cjn = cj * CA1 - sj * SA1;
        sj = sj * CA1 + cj * SA1;
        cj = cjn;
    }

    // ---- normalize + store ----
    #pragma unroll
    for (int t = 0; t < 4; ++t) {
        int row = g + 4 * t;
        if (row < W) {
            float rdt = __fdividef(1.0f, fmaxf(dn[t], EPS));
            ull r2 = pack2(rdt, rdt);
            ulonglong2 o0, o1;
            o0.x = mul2(acc[t][0], r2); o0.y = mul2(acc[t][1], r2);
            o1.x = mul2(acc[t][2], r2); o1.y = mul2(acc[t][3], r2);
            ulonglong2* op = (ulonglong2*)(out + base + row * DIM + doff);
            op[0] = o0; op[1] = o1;
        }
    }
}

extern "C" void kernel_launch(void* const* d_in, const int* in_sizes, int n_in,
                              void* d_out, int out_size) {
    const float* q = (const float*)d_in[0];
    const float* k = (const float*)d_in[1];
    const float* v = (const float*)d_in[2];
    float* out = (float*)d_out;

    int n = in_sizes[0];            // B*H*L*D
    int G = n / (W * DIM);          // number of attention blocks (20480)
    int grid = (G + WARPS_PER_CTA - 1) / WARPS_PER_CTA;
    robust_attn_kernel<<<grid, NTHREADS>>>(q, k, v, out, G);
}